// round 5
// baseline (speedup 1.0000x reference)
#include <cuda_runtime.h>
#include <math.h>
#include <stdint.h>

// Problem constants (fixed by the dataset)
#define NN 16384      // nodes per set
#define DD 256        // model dim
#define EE 131072     // edges per relation
#define HH 8          // heads
#define HDIM 32       // head dim
#define IM 682        // SwiGLU intermediate

// ---------------- scratch (static device globals; no allocations) ----------
__device__ float g_q[NN * DD];          // q (contiguous [n][h*32+d])
__device__ float g_k[NN * DD];          // k
__device__ float g_v[NN * DD];          // v
__device__ float g_scores[EE * HH];
__device__ float g_s[NN * HH];
__device__ float g_agg[NN * DD];
__device__ float g_x1[NN * DD];
__device__ float g_x2[NN * DD];
__device__ float g_tmp[NN * DD];
__device__ float g_h1[NN * IM];
__device__ float g_h2[NN * IM];

__device__ __forceinline__ uint32_t f2tf32(float f) {
    uint32_t r;
    asm("cvt.rna.tf32.f32 %0, %1;" : "=r"(r) : "f"(f));
    return r;
}

// ---------------- TF32 tensor-core GEMM -------------------------------------
// C = A[M,K] @ B[K,N], row-major fp32, tf32 mma. 128x128 tile, BK=32, 8 warps.
// MODE 0: plain store to C0.
// MODE 1: kv de-interleave: col c -> h=c>>6, d=(c&63)>>1, (c&1)? C1(v):C0(k), idx h*32+d
// MODE 2: qkv de-interleave: col c -> h=c/96, r=c%96, d=r/3, w=r%3 -> C0/C1/C2
#define BK 32
#define APAD 40    // word stride of As rows (conflict-free LDS.64 frag loads)
#define BPAD 132

// k-pair interleave position: (k, k+4) adjacent within each 8-k atom
__device__ __forceinline__ int kpos(int k) {
    return (k >> 3) * 8 + ((k & 3) << 1) + ((k >> 2) & 1);
}

template <int MODE>
__global__ __launch_bounds__(256)
void tgemm(const float* __restrict__ A, const float* __restrict__ B,
           float* __restrict__ C0, float* __restrict__ C1, float* __restrict__ C2,
           int M, int N, int K) {
    __shared__ uint32_t As[128][APAD];   // [m][k-interleaved]
    __shared__ uint32_t Bs[BK][BPAD];    // [k][n]

    const int tid  = threadIdx.x;
    const int lane = tid & 31;
    const int wid  = tid >> 5;
    const int warpM = wid & 1;
    const int warpN = wid >> 1;
    const int g   = lane >> 2;
    const int tig = lane & 3;

    const int rowBase = blockIdx.y * 128;
    const int colBase = blockIdx.x * 128;

    float acc[4][4][4];
    #pragma unroll
    for (int i = 0; i < 4; i++)
        #pragma unroll
        for (int j = 0; j < 4; j++)
            #pragma unroll
            for (int r = 0; r < 4; r++) acc[i][j][r] = 0.0f;

    for (int k0 = 0; k0 < K; k0 += BK) {
        __syncthreads();
        // A tile: 128 rows x 16 k-pairs (float2), store pair-interleaved
        #pragma unroll
        for (int i = 0; i < 8; i++) {
            int l  = tid + i * 256;
            int r  = l >> 4;
            int c2 = l & 15;
            int gr = rowBase + r;
            int gk = k0 + 2 * c2;
            float2 vv = make_float2(0.0f, 0.0f);
            if (gr < M && gk < K) vv = *(const float2*)(A + (size_t)gr * K + gk);
            As[r][kpos(2 * c2)]     = f2tf32(vv.x);
            As[r][kpos(2 * c2 + 1)] = f2tf32(vv.y);
        }
        // B tile: 32 k x 64 n-pairs (float2)
        #pragma unroll
        for (int i = 0; i < 8; i++) {
            int l  = tid + i * 256;
            int kk = l >> 6;
            int c2 = l & 63;
            int gk = k0 + kk;
            int gc = colBase + 2 * c2;
            float2 vv = make_float2(0.0f, 0.0f);
            if (gk < K && gc < N) vv = *(const float2*)(B + (size_t)gk * N + gc);
            Bs[kk][2 * c2]     = f2tf32(vv.x);
            Bs[kk][2 * c2 + 1] = f2tf32(vv.y);
        }
        __syncthreads();

        #pragma unroll
        for (int ka = 0; ka < 4; ka++) {
            const int kb = ka * 8;
            const int aoff = kb + 2 * tig;
            uint32_t a[4][4], b[4][2];
            #pragma unroll
            for (int ma = 0; ma < 4; ma++) {
                int m0 = warpM * 64 + ma * 16 + g;
                uint2 v1 = *(const uint2*)&As[m0][aoff];
                uint2 v2 = *(const uint2*)&As[m0 + 8][aoff];
                a[ma][0] = v1.x; a[ma][2] = v1.y;
                a[ma][1] = v2.x; a[ma][3] = v2.y;
            }
            #pragma unroll
            for (int na = 0; na < 4; na++) {
                int n0 = warpN * 32 + na * 8 + g;
                b[na][0] = Bs[kb + tig][n0];
                b[na][1] = Bs[kb + tig + 4][n0];
            }
            #pragma unroll
            for (int ma = 0; ma < 4; ma++)
                #pragma unroll
                for (int na = 0; na < 4; na++) {
                    asm volatile(
                        "mma.sync.aligned.m16n8k8.row.col.f32.tf32.tf32.f32 "
                        "{%0,%1,%2,%3}, {%4,%5,%6,%7}, {%8,%9}, {%0,%1,%2,%3};\n"
                        : "+f"(acc[ma][na][0]), "+f"(acc[ma][na][1]),
                          "+f"(acc[ma][na][2]), "+f"(acc[ma][na][3])
                        : "r"(a[ma][0]), "r"(a[ma][1]), "r"(a[ma][2]), "r"(a[ma][3]),
                          "r"(b[na][0]), "r"(b[na][1]));
                }
        }
    }

    // ---- store
    #pragma unroll
    for (int ma = 0; ma < 4; ma++) {
        int r0 = rowBase + warpM * 64 + ma * 16 + g;
        #pragma unroll
        for (int na = 0; na < 4; na++) {
            int c = colBase + warpN * 32 + na * 8 + tig * 2;
            if (c >= N) continue;
            if (MODE == 0) {
                if (r0 < M)
                    *(float2*)(C0 + (size_t)r0 * N + c) = make_float2(acc[ma][na][0], acc[ma][na][1]);
                if (r0 + 8 < M)
                    *(float2*)(C0 + (size_t)(r0 + 8) * N + c) = make_float2(acc[ma][na][2], acc[ma][na][3]);
            } else {
                #pragma unroll
                for (int e = 0; e < 4; e++) {
                    int cc = c + (e & 1);
                    int rr = r0 + (e >> 1) * 8;
                    if (rr >= M) continue;
                    float val = acc[ma][na][e];
                    if (MODE == 1) {
                        int h = cc >> 6, rm = cc & 63, d = rm >> 1;
                        float* dst = (rm & 1) ? C1 : C0;
                        dst[(size_t)rr * DD + h * HDIM + d] = val;
                    } else {
                        int h = cc / 96, rm = cc % 96, d = rm / 3, w = rm % 3;
                        float* dst = (w == 0) ? C0 : ((w == 1) ? C1 : C2);
                        dst[(size_t)rr * DD + h * HDIM + d] = val;
                    }
                }
            }
        }
    }
}

// ---------------- reset: agg=0, s=0 -----------------------------------------
__global__ void reset_kernel(float* s, float* agg) {
    int i = blockIdx.x * blockDim.x + threadIdx.x;   // NN*DD threads
    agg[i] = 0.0f;
    if (i < NN * HH) s[i] = 0.0f;
}

// ---------------- reciprocal of softmax denominators ------------------------
__global__ void rcp_kernel(float* __restrict__ s) {
    int i = blockIdx.x * blockDim.x + threadIdx.x;
    if (i < NN * HH) s[i] = __frcp_rn(s[i]);
}

// ---------------- edge kernels (contiguous [n][h*32+d] layouts) -------------
// warp per edge; 4 lanes per head; lane handles 8 consecutive dims.
// No max-subtraction: scores are O(10), exp is safe in fp32; softmax is
// shift-invariant so the result matches the reference.
__global__ void cross_scores_kernel(const float* __restrict__ Q, const float* __restrict__ Kk,
                                    const int* __restrict__ src, const int* __restrict__ dst,
                                    float* __restrict__ scores, float* __restrict__ s,
                                    float scale) {
    int e = (blockIdx.x * blockDim.x + threadIdx.x) >> 5;
    int lane = threadIdx.x & 31;
    if (e >= EE) return;
    int sn = src[e], tn = dst[e];
    const float4* q4 = (const float4*)(Q  + (size_t)tn * DD);
    const float4* k4 = (const float4*)(Kk + (size_t)sn * DD);
    float4 qa = q4[2 * lane], qb = q4[2 * lane + 1];
    float4 ka = k4[2 * lane], kb = k4[2 * lane + 1];
    float p = qa.x * ka.x + qa.y * ka.y + qa.z * ka.z + qa.w * ka.w
            + qb.x * kb.x + qb.y * kb.y + qb.z * kb.z + qb.w * kb.w;
    p += __shfl_xor_sync(0xFFFFFFFFu, p, 1);
    p += __shfl_xor_sync(0xFFFFFFFFu, p, 2);
    if ((lane & 3) == 0) {
        int h = lane >> 2;
        float ev = __expf(p * scale);
        scores[(size_t)e * HH + h] = ev;
        atomicAdd(&s[tn * HH + h], ev);
    }
}

__global__ void self_scores_kernel(const float* __restrict__ Q, const float* __restrict__ Kk,
                                   const float* __restrict__ attr,
                                   const int* __restrict__ src, const int* __restrict__ dst,
                                   float* __restrict__ scores, float* __restrict__ s) {
    int e = (blockIdx.x * blockDim.x + threadIdx.x) >> 5;
    int lane = threadIdx.x & 31;
    if (e >= EE) return;
    int sn = src[e], tn = dst[e];
    const float4* q4 = (const float4*)(Q    + (size_t)tn * DD);
    const float4* k4 = (const float4*)(Kk   + (size_t)sn * DD);
    const float4* a4 = (const float4*)(attr + (size_t)e  * DD);
    float4 qa = q4[2 * lane], qb = q4[2 * lane + 1];
    float4 ka = k4[2 * lane], kb = k4[2 * lane + 1];
    float4 aa = a4[2 * lane], ab = a4[2 * lane + 1];
    float p = qa.x * ka.x * aa.x + qa.y * ka.y * aa.y + qa.z * ka.z * aa.z + qa.w * ka.w * aa.w
            + qb.x * kb.x * ab.x + qb.y * kb.y * ab.y + qb.z * kb.z * ab.z + qb.w * kb.w * ab.w;
    p += __shfl_xor_sync(0xFFFFFFFFu, p, 1);
    p += __shfl_xor_sync(0xFFFFFFFFu, p, 2);
    if ((lane & 3) == 0) {
        int h = lane >> 2;
        float ev = __expf(p);   // no 1/sqrt(hd) in SelfMHA
        scores[(size_t)e * HH + h] = ev;
        atomicAdd(&s[tn * HH + h], ev);
    }
}

__global__ void agg_kernel(const float* __restrict__ scores, const float* __restrict__ rsum,
                           const float* __restrict__ V,
                           const int* __restrict__ src, const int* __restrict__ dst,
                           float* __restrict__ agg) {
    int e = (blockIdx.x * blockDim.x + threadIdx.x) >> 5;
    int lane = threadIdx.x & 31;
    if (e >= EE) return;
    int sn = src[e], tn = dst[e];
    int h = lane >> 2;
    float w = scores[(size_t)e * HH + h] * rsum[tn * HH + h];
    const float4* v4 = (const float4*)(V + (size_t)sn * DD);
    float4 va = v4[2 * lane], vb = v4[2 * lane + 1];
    float* dstp = agg + (size_t)tn * DD + lane * 8;
    atomicAdd(dstp + 0, w * va.x);
    atomicAdd(dstp + 1, w * va.y);
    atomicAdd(dstp + 2, w * va.z);
    atomicAdd(dstp + 3, w * va.w);
    atomicAdd(dstp + 4, w * vb.x);
    atomicAdd(dstp + 5, w * vb.y);
    atomicAdd(dstp + 6, w * vb.z);
    atomicAdd(dstp + 7, w * vb.w);
}

// ---------------- residual + RMSNorm: out = rmsnorm(a+b) * g ----------------
__global__ void add_rmsnorm_kernel(const float* __restrict__ a, const float* __restrict__ b,
                                   const float* __restrict__ g, float* __restrict__ out) {
    int row = blockIdx.x;
    int d = threadIdx.x;
    float x = a[(size_t)row * DD + d] + b[(size_t)row * DD + d];
    float v = x * x;
    __shared__ float red[8];
    #pragma unroll
    for (int o = 16; o; o >>= 1) v += __shfl_xor_sync(0xFFFFFFFFu, v, o);
    if ((d & 31) == 0) red[d >> 5] = v;
    __syncthreads();
    if (d < 8) {
        float t = red[d];
        #pragma unroll
        for (int o = 4; o; o >>= 1) t += __shfl_xor_sync(0xFFu, t, o);
        if (d == 0) red[0] = t;
    }
    __syncthreads();
    float norm = sqrtf(red[0]) * 0.0625f;
    float inv = 1.0f / fmaxf(norm, 1e-8f);
    out[(size_t)row * DD + d] = x * inv * g[d];
}

// ---------------- SwiGLU activation -----------------------------------------
__global__ void swiglu_act_kernel(float* __restrict__ h1, const float* __restrict__ h2, int n) {
    int i = blockIdx.x * blockDim.x + threadIdx.x;
    if (i >= n) return;
    float x = h1[i];
    h1[i] = x * (1.0f / (1.0f + __expf(-x))) * h2[i];
}

// ---------------- launch ----------------------------------------------------
static inline dim3 gg128(int M, int Ncols) { return dim3((Ncols + 127) / 128, (M + 127) / 128); }

extern "C" void kernel_launch(void* const* d_in, const int* in_sizes, int n_in,
                              void* d_out, int out_size) {
    const float* root      = (const float*)d_in[0];
    const float* node      = (const float*)d_in[1];
    const float* fringe    = (const float*)d_in[2];
    const int*   ntr_idx   = (const int*)d_in[3];
    const int*   rtr_idx   = (const int*)d_in[4];
    const int*   rtf_idx   = (const int*)d_in[5];
    const float* edge_attr = (const float*)d_in[6];
    const float* ntr_wq    = (const float*)d_in[7];
    const float* ntr_wkv   = (const float*)d_in[8];
    const float* ntr_wout  = (const float*)d_in[9];
    const float* ntr_g     = (const float*)d_in[10];
    const float* rtr_wqkv  = (const float*)d_in[11];
    const float* rtr_wout  = (const float*)d_in[12];
    const float* rtr_g     = (const float*)d_in[13];
    const float* ffn_win   = (const float*)d_in[14];
    const float* ffn_v     = (const float*)d_in[15];
    const float* ffn_wout  = (const float*)d_in[16];
    const float* ffn_g     = (const float*)d_in[17];
    const float* rtf_wq    = (const float*)d_in[18];
    const float* rtf_wkv   = (const float*)d_in[19];
    const float* rtf_wout  = (const float*)d_in[20];
    float* out = (float*)d_out;

    float *q, *k, *v, *scores, *s, *agg, *x1, *x2, *tmp, *h1, *h2;
    cudaGetSymbolAddress((void**)&q,      g_q);
    cudaGetSymbolAddress((void**)&k,      g_k);
    cudaGetSymbolAddress((void**)&v,      g_v);
    cudaGetSymbolAddress((void**)&scores, g_scores);
    cudaGetSymbolAddress((void**)&s,      g_s);
    cudaGetSymbolAddress((void**)&agg,    g_agg);
    cudaGetSymbolAddress((void**)&x1,     g_x1);
    cudaGetSymbolAddress((void**)&x2,     g_x2);
    cudaGetSymbolAddress((void**)&tmp,    g_tmp);
    cudaGetSymbolAddress((void**)&h1,     g_h1);
    cudaGetSymbolAddress((void**)&h2,     g_h2);

    const float iscale = 0.17677669529663687f;  // 1/sqrt(32)
    const int edgeBlocks = EE / 8;
    const int resetBlocks = (NN * DD) / 256;
    const int nhBlocks = (NN * HH) / 256;

    // ===== stage 1: nodes_to_root CrossMHA + residual rmsnorm -> x1 =====
    tgemm<0><<<gg128(NN, DD), 256>>>(root, ntr_wq, q, 0, 0, NN, DD, DD);
    tgemm<1><<<gg128(NN, 2 * DD), 256>>>(node, ntr_wkv, k, v, 0, NN, 2 * DD, DD);
    reset_kernel<<<resetBlocks, 256>>>(s, agg);
    cross_scores_kernel<<<edgeBlocks, 256>>>(q, k, ntr_idx, ntr_idx + EE, scores, s, iscale);
    rcp_kernel<<<nhBlocks, 256>>>(s);
    agg_kernel<<<edgeBlocks, 256>>>(scores, s, v, ntr_idx, ntr_idx + EE, agg);
    tgemm<0><<<gg128(NN, DD), 256>>>(agg, ntr_wout, tmp, 0, 0, NN, DD, DD);
    add_rmsnorm_kernel<<<NN, 256>>>(root, tmp, ntr_g, x1);

    // ===== stage 2: roots_to_root SelfMHA + residual rmsnorm -> x2 =====
    tgemm<2><<<gg128(NN, 3 * DD), 256>>>(x1, rtr_wqkv, q, k, v, NN, 3 * DD, DD);
    reset_kernel<<<resetBlocks, 256>>>(s, agg);
    self_scores_kernel<<<edgeBlocks, 256>>>(q, k, edge_attr, rtr_idx, rtr_idx + EE, scores, s);
    rcp_kernel<<<nhBlocks, 256>>>(s);
    agg_kernel<<<edgeBlocks, 256>>>(scores, s, v, rtr_idx, rtr_idx + EE, agg);
    tgemm<0><<<gg128(NN, DD), 256>>>(agg, rtr_wout, tmp, 0, 0, NN, DD, DD);
    add_rmsnorm_kernel<<<NN, 256>>>(x1, tmp, rtr_g, x2);

    // ===== stage 3: SwiGLU FFN (on root_features) + residual rmsnorm -> out =====
    tgemm<0><<<gg128(NN, IM), 256>>>(root, ffn_win, h1, 0, 0, NN, IM, DD);
    tgemm<0><<<gg128(NN, IM), 256>>>(root, ffn_v, h2, 0, 0, NN, IM, DD);
    swiglu_act_kernel<<<(NN * IM + 255) / 256, 256>>>(h1, h2, NN * IM);
    tgemm<0><<<gg128(NN, DD), 256>>>(h1, ffn_wout, tmp, 0, 0, NN, DD, IM);
    add_rmsnorm_kernel<<<NN, 256>>>(tmp, x2, ffn_g, out);

    // ===== stage 4: root_to_fringe CrossMHA -> out[N*D : 2*N*D] =====
    tgemm<0><<<gg128(NN, DD), 256>>>(fringe, rtf_wq, q, 0, 0, NN, DD, DD);
    tgemm<1><<<gg128(NN, 2 * DD), 256>>>(root, rtf_wkv, k, v, 0, NN, 2 * DD, DD);
    reset_kernel<<<resetBlocks, 256>>>(s, agg);
    cross_scores_kernel<<<edgeBlocks, 256>>>(q, k, rtf_idx, rtf_idx + EE, scores, s, iscale);
    rcp_kernel<<<nhBlocks, 256>>>(s);
    agg_kernel<<<edgeBlocks, 256>>>(scores, s, v, rtf_idx, rtf_idx + EE, agg);
    tgemm<0><<<gg128(NN, DD), 256>>>(agg, rtf_wout, out + (size_t)NN * DD, 0, 0, NN, DD, DD);
}